// round 16
// baseline (speedup 1.0000x reference)
#include <cuda_runtime.h>
#include <cuda_fp16.h>
#include <cstdint>
#include <math.h>

// Problem constants
#define B_  4
#define N_  1024
#define E_  1024
#define H_  16
#define D_  64
#define MTOT (B_ * N_)   // 4096
#define BHN  (B_ * H_)   // 64
#define LOG2E 1.44269504088896f

// ==================== mma.sync / ldmatrix / cp.async helpers (fp16) ====================
__device__ __forceinline__ uint32_t smem_to_u32(const void* p) {
    uint32_t a;
    asm("{ .reg .u64 t; cvta.to.shared.u64 t, %1; cvt.u32.u64 %0, t; }" : "=r"(a) : "l"(p));
    return a;
}
#define LDSM_X4(R, ADDR) \
    asm volatile("ldmatrix.sync.aligned.m8n8.x4.shared.b16 {%0,%1,%2,%3}, [%4];" \
        : "=r"((R)[0]), "=r"((R)[1]), "=r"((R)[2]), "=r"((R)[3]) : "r"(ADDR))
#define MMA_F16(D, A, B0, B1) \
    asm("mma.sync.aligned.m16n8k16.row.col.f32.f16.f16.f32 " \
        "{%0,%1,%2,%3}, {%4,%5,%6,%7}, {%8,%9}, {%0,%1,%2,%3};" \
        : "+f"((D)[0]), "+f"((D)[1]), "+f"((D)[2]), "+f"((D)[3]) \
        : "r"((A)[0]), "r"((A)[1]), "r"((A)[2]), "r"((A)[3]), "r"(B0), "r"(B1))
#define CP_A16(DST, SRC) \
    asm volatile("cp.async.ca.shared.global [%0], [%1], 16;" :: "r"(DST), "l"(SRC))
#define CP_COMMIT() asm volatile("cp.async.commit_group;" ::: "memory")
#define CP_WAIT0()  asm volatile("cp.async.wait_group 0;" ::: "memory")

// pack two fp32 -> fp16x2 (lo element in low 16 bits)
__device__ __forceinline__ uint32_t packh(float lo, float hi) {
    uint32_t d;
    asm("cvt.rn.f16x2.f32 %0, %1, %2;" : "=r"(d) : "f"(hi), "f"(lo));
    return d;
}
__device__ __forceinline__ float toh(float v) {
    return __half2float(__float2half(v));
}

// ==================== scratch (device globals) ====================
__device__ __half g_xh[MTOT * E_], g_xl[MTOT * E_];
__device__ __half g_wqh[E_ * E_], g_wql[E_ * E_];
__device__ __half g_wkh[E_ * E_], g_wkl[E_ * E_];
__device__ __half g_wvh[E_ * E_];
__device__ __half g_woh[E_ * E_];
__device__ __half g_qh[MTOT * E_], g_ql[MTOT * E_];     // Q pre-scaled by log2(e)
__device__ __half g_kh[MTOT * E_], g_kl[MTOT * E_];
__device__ __half g_vt[BHN * D_ * N_];        // V^T single fp16: [bh][d][tok]
__device__ __half g_c[MTOT * E_];             // ctx single fp16

// ==================== merged fp32 -> fp16 hi/lo split (4 float4 / thread) ====================
// lo residual stored only for x, Wq, Wk (V/out projections are 1-term)
__global__ __launch_bounds__(256)
void split_all(const float* __restrict__ x,
               const float* __restrict__ wq, const float* __restrict__ wk,
               const float* __restrict__ wv, const float* __restrict__ wo,
               __half* __restrict__ xh, __half* __restrict__ xl,
               __half* __restrict__ wqh, __half* __restrict__ wql,
               __half* __restrict__ wkh, __half* __restrict__ wkl,
               __half* __restrict__ wvh, __half* __restrict__ woh)
{
    int blk = blockIdx.x;
    const float* in;
    __half *hi, *lo;
    int base;
    if (blk < 1024)      { in = x;  hi = xh;  lo = xl;  base = blk; }
    else if (blk < 1280) { in = wq; hi = wqh; lo = wql; base = blk - 1024; }
    else if (blk < 1536) { in = wk; hi = wkh; lo = wkl; base = blk - 1280; }
    else if (blk < 1792) { in = wv; hi = wvh; lo = nullptr; base = blk - 1536; }
    else                 { in = wo; hi = woh; lo = nullptr; base = blk - 1792; }

    const long off = (long)base * 4096 + threadIdx.x * 4;
    float4 v[4];
    #pragma unroll
    for (int j = 0; j < 4; j++)
        v[j] = *reinterpret_cast<const float4*>(in + off + j * 1024);
    #pragma unroll
    for (int j = 0; j < 4; j++) {
        long i = off + j * 1024;
        float vv[4] = {v[j].x, v[j].y, v[j].z, v[j].w};
        uint2 hw;
        hw.x = packh(vv[0], vv[1]);
        hw.y = packh(vv[2], vv[3]);
        *reinterpret_cast<uint2*>(hi + i) = hw;
        if (lo) {
            uint2 lw;
            lw.x = packh(vv[0] - toh(vv[0]), vv[1] - toh(vv[1]));
            lw.y = packh(vv[2] - toh(vv[2]), vv[3] - toh(vv[3]));
            *reinterpret_cast<uint2*>(lo + i) = lw;
        }
    }
}

// ==================== pipelined split-fp16 GEMM core (QKV) ====================
#define GSTR   80
#define G_ALO  10240
#define G_BHI  20480
#define G_BLO  30720
#define GSTAGE 40960
#define GSMEM  (2 * GSTAGE)   // 81920

struct GemmAcc { float a[2][8][4]; };

__device__ __forceinline__ void gemm_issue(uint32_t sbase, int stg,
    const __half* pAh, const __half* pAl,
    const __half* pBh, const __half* pBl, int tid, int nterms)
{
    const uint32_t s0 = sbase + stg * GSTAGE;
    #pragma unroll
    for (int i = 0; i < 2; i++) {
        int c = tid + i * 256;
        int r = c >> 2, k8 = c & 3;
        uint32_t so = r * GSTR + k8 * 16;
        CP_A16(s0 + so,          pAh + (long)r * E_ + k8 * 8);
        CP_A16(s0 + G_BHI + so,  pBh + (long)r * E_ + k8 * 8);
        if (nterms >= 3) CP_A16(s0 + G_ALO + so, pAl + (long)r * E_ + k8 * 8);
        if (nterms >= 2) CP_A16(s0 + G_BLO + so, pBl + (long)r * E_ + k8 * 8);
    }
}

// nterms: 3 = HH+HL+LH (Q/K), 1 = HH only (V)
__device__ __forceinline__ void gemm_compute(uint32_t sbase, int stg, GemmAcc& acc,
                                             int wm, int wn, int lrow, int lk8b, int nterms)
{
    const uint32_t s0 = sbase + stg * GSTAGE;

    uint32_t aH[2][2][4], aL[2][2][4];   // [ks][mi]
    #pragma unroll
    for (int ks = 0; ks < 2; ks++)
        #pragma unroll
        for (int mi = 0; mi < 2; mi++) {
            uint32_t ao = s0 + (uint32_t)(wm * 32 + mi * 16 + lrow) * GSTR + ks * 32 + lk8b;
            LDSM_X4(aH[ks][mi], ao);
            if (nterms >= 3) LDSM_X4(aL[ks][mi], ao + G_ALO);
        }

    uint32_t bH[2][4], bL[2][4];
    {
        uint32_t bo = s0 + G_BHI + (uint32_t)(wn * 64 + lrow) * GSTR + lk8b;
        LDSM_X4(bH[0], bo);
        if (nterms >= 2) LDSM_X4(bL[0], bo + (G_BLO - G_BHI));
    }

    #pragma unroll
    for (int it = 0; it < 8; it++) {
        const int ks = it >> 2, nj = it & 3;
        const int cur = it & 1, nxt = cur ^ 1;
        if (it < 7) {
            const int it2 = it + 1, ks2 = it2 >> 2, nj2 = it2 & 3;
            uint32_t bo = s0 + G_BHI + (uint32_t)(wn * 64 + nj2 * 16 + lrow) * GSTR + ks2 * 32 + lk8b;
            LDSM_X4(bH[nxt], bo);
            if (nterms >= 2) LDSM_X4(bL[nxt], bo + (G_BLO - G_BHI));
        }
        MMA_F16(acc.a[0][2 * nj],     aH[ks][0], bH[cur][0], bH[cur][2]);
        MMA_F16(acc.a[0][2 * nj + 1], aH[ks][0], bH[cur][1], bH[cur][3]);
        MMA_F16(acc.a[1][2 * nj],     aH[ks][1], bH[cur][0], bH[cur][2]);
        MMA_F16(acc.a[1][2 * nj + 1], aH[ks][1], bH[cur][1], bH[cur][3]);
        if (nterms >= 2) {
            MMA_F16(acc.a[0][2 * nj],     aH[ks][0], bL[cur][0], bL[cur][2]);
            MMA_F16(acc.a[0][2 * nj + 1], aH[ks][0], bL[cur][1], bL[cur][3]);
            MMA_F16(acc.a[1][2 * nj],     aH[ks][1], bL[cur][0], bL[cur][2]);
            MMA_F16(acc.a[1][2 * nj + 1], aH[ks][1], bL[cur][1], bL[cur][3]);
        }
        if (nterms >= 3) {
            MMA_F16(acc.a[0][2 * nj],     aL[ks][0], bH[cur][0], bH[cur][2]);
            MMA_F16(acc.a[0][2 * nj + 1], aL[ks][0], bH[cur][1], bH[cur][3]);
            MMA_F16(acc.a[1][2 * nj],     aL[ks][1], bH[cur][0], bH[cur][2]);
            MMA_F16(acc.a[1][2 * nj + 1], aL[ks][1], bH[cur][1], bH[cur][3]);
        }
    }
}

// ---- merged QKV projection: Q/K 3-term, V 1-term. Q scaled by log2(e). ----
__global__ void __launch_bounds__(256, 2)
gemm_qkv(const __half* __restrict__ Ah, const __half* __restrict__ Al,
         const __half* __restrict__ wqh, const __half* __restrict__ wql,
         const __half* __restrict__ wkh, const __half* __restrict__ wkl,
         const __half* __restrict__ wvh,
         const float* __restrict__ bq, const float* __restrict__ bk, const float* __restrict__ bv,
         __half* __restrict__ qh, __half* __restrict__ ql,
         __half* __restrict__ kh, __half* __restrict__ kl,
         __half* __restrict__ vt)
{
    extern __shared__ char smem[];
    const uint32_t sbase = smem_to_u32(smem);
    const int tid = threadIdx.x, warp = tid >> 5, lane = tid & 31;
    const int wm = warp & 3, wn = warp >> 2;
    const int lrow = (lane & 7) | (((lane >> 3) & 1) << 3);
    const int lk8b = (lane >> 4) * 16;

    const int widx = blockIdx.x >> 3;          // 0=Q, 1=K, 2=V
    const int col0 = (blockIdx.x & 7) * 128;
    const int row0 = blockIdx.y * 128;
    const int nterms = (widx == 2) ? 1 : 3;

    const __half* Bh = (widx == 0) ? wqh : (widx == 1) ? wkh : wvh;
    const __half* Bl = (widx == 0) ? wql : wkl;   // unused when nterms==1
    const float* bias = (widx == 0) ? bq : (widx == 1) ? bk : bv;

    GemmAcc acc;
    #pragma unroll
    for (int mi = 0; mi < 2; mi++)
        #pragma unroll
        for (int nj = 0; nj < 8; nj++)
            #pragma unroll
            for (int r = 0; r < 4; r++) acc.a[mi][nj][r] = 0.f;

    const __half* pAh = Ah + (long)row0 * E_;
    const __half* pAl = Al + (long)row0 * E_;
    const __half* pBh = Bh + (long)col0 * E_;
    const __half* pBl = Bl + (long)col0 * E_;

    const int nch = E_ >> 5;
    gemm_issue(sbase, 0, pAh, pAl, pBh, pBl, tid, nterms);
    CP_COMMIT();
    CP_WAIT0();
    __syncthreads();
    for (int kc = 0; kc < nch; kc++) {
        if (kc + 1 < nch) {
            gemm_issue(sbase, (kc + 1) & 1, pAh + (kc + 1) * 32, pAl + (kc + 1) * 32,
                       pBh + (kc + 1) * 32, pBl + (kc + 1) * 32, tid, nterms);
            CP_COMMIT();
        }
        gemm_compute(sbase, kc & 1, acc, wm, wn, lrow, lk8b, nterms);
        if (kc + 1 < nch) { CP_WAIT0(); __syncthreads(); }
    }

    const float qscale = (widx == 0) ? LOG2E : 1.0f;
    #pragma unroll
    for (int mi = 0; mi < 2; mi++) {
        int rg = row0 + wm * 32 + mi * 16 + (lane >> 2);
        #pragma unroll
        for (int nf = 0; nf < 8; nf++) {
            int cg = col0 + wn * 64 + nf * 8 + (lane & 3) * 2;
            #pragma unroll
            for (int rr = 0; rr < 2; rr++) {
                int m = rg + rr * 8;
                float v0 = (acc.a[mi][nf][rr * 2 + 0] + bias[cg])     * qscale;
                float v1 = (acc.a[mi][nf][rr * 2 + 1] + bias[cg + 1]) * qscale;
                if (widx != 2) {
                    __half* dh = (widx == 0) ? qh : kh;
                    __half* dl = (widx == 0) ? ql : kl;
                    long o = (long)m * E_ + cg;
                    *reinterpret_cast<uint32_t*>(dh + o) = packh(v0, v1);
                    *reinterpret_cast<uint32_t*>(dl + o) = packh(v0 - toh(v0), v1 - toh(v1));
                } else {
                    int b = m >> 10, tok = m & 1023;
                    int hh = cg >> 6, dc0 = cg & 63;
                    long o0 = ((long)(b * H_ + hh) * D_ + dc0) * N_ + tok;
                    vt[o0] = __float2half(v0);
                    vt[o0 + N_] = __float2half(v1);
                }
            }
        }
    }
}

// ---- output projection: 1-term ----
#define OSTR   80
#define O_B    10240
#define OSTAGE 20480
#define OSMEM  (2 * OSTAGE)   // 40960

__global__ void __launch_bounds__(256, 2)
gemm_out(const __half* __restrict__ A, const __half* __restrict__ Bh,
         const float* __restrict__ bias, float* __restrict__ Cf)
{
    extern __shared__ char smem[];
    const uint32_t sbase = smem_to_u32(smem);
    const int tid = threadIdx.x, warp = tid >> 5, lane = tid & 31;
    const int wm = warp & 3, wn = warp >> 2;
    const int lrow = (lane & 7) | (((lane >> 3) & 1) << 3);
    const int lk8b = (lane >> 4) * 16;

    const int col0 = blockIdx.x * 128;
    const int row0 = blockIdx.y * 128;

    GemmAcc acc;
    #pragma unroll
    for (int mi = 0; mi < 2; mi++)
        #pragma unroll
        for (int nj = 0; nj < 8; nj++)
            #pragma unroll
            for (int r = 0; r < 4; r++) acc.a[mi][nj][r] = 0.f;

    const __half* pA  = A  + (long)row0 * E_;
    const __half* pBh = Bh + (long)col0 * E_;

    auto issue = [&](int stg, int kc) {
        const uint32_t s0 = sbase + stg * OSTAGE;
        #pragma unroll
        for (int i = 0; i < 2; i++) {
            int c = tid + i * 256;
            int r = c >> 2, k8 = c & 3;
            uint32_t so = r * OSTR + k8 * 16;
            CP_A16(s0 + so,        pA  + (long)r * E_ + kc * 32 + k8 * 8);
            CP_A16(s0 + O_B + so,  pBh + (long)r * E_ + kc * 32 + k8 * 8);
        }
    };

    const int nch = E_ >> 5;
    issue(0, 0);
    CP_COMMIT();
    CP_WAIT0();
    __syncthreads();
    for (int kc = 0; kc < nch; kc++) {
        if (kc + 1 < nch) { issue((kc + 1) & 1, kc + 1); CP_COMMIT(); }
        {
            const uint32_t s0 = sbase + (kc & 1) * OSTAGE;
            uint32_t aF[2][2][4];
            #pragma unroll
            for (int ks = 0; ks < 2; ks++)
                #pragma unroll
                for (int mi = 0; mi < 2; mi++) {
                    uint32_t ao = s0 + (uint32_t)(wm * 32 + mi * 16 + lrow) * OSTR + ks * 32 + lk8b;
                    LDSM_X4(aF[ks][mi], ao);
                }
            uint32_t bB[2][4];
            {
                uint32_t bo = s0 + O_B + (uint32_t)(wn * 64 + lrow) * OSTR + lk8b;
                LDSM_X4(bB[0], bo);
            }
            #pragma unroll
            for (int it = 0; it < 8; it++) {
                const int ks = it >> 2, nj = it & 3;
                const int cur = it & 1, nxt = cur ^ 1;
                if (it < 7) {
                    const int it2 = it + 1, ks2 = it2 >> 2, nj2 = it2 & 3;
                    uint32_t bo = s0 + O_B + (uint32_t)(wn * 64 + nj2 * 16 + lrow) * OSTR + ks2 * 32 + lk8b;
                    LDSM_X4(bB[nxt], bo);
                }
                MMA_F16(acc.a[0][2 * nj],     aF[ks][0], bB[cur][0], bB[cur][2]);
                MMA_F16(acc.a[0][2 * nj + 1], aF[ks][0], bB[cur][1], bB[cur][3]);
                MMA_F16(acc.a[1][2 * nj],     aF[ks][1], bB[cur][0], bB[cur][2]);
                MMA_F16(acc.a[1][2 * nj + 1], aF[ks][1], bB[cur][1], bB[cur][3]);
            }
        }
        if (kc + 1 < nch) { CP_WAIT0(); __syncthreads(); }
    }

    #pragma unroll
    for (int mi = 0; mi < 2; mi++) {
        int rg = row0 + wm * 32 + mi * 16 + (lane >> 2);
        #pragma unroll
        for (int nf = 0; nf < 8; nf++) {
            int cg = col0 + wn * 64 + nf * 8 + (lane & 3) * 2;
            #pragma unroll
            for (int rr = 0; rr < 2; rr++) {
                int m = rg + rr * 8;
                float2 v;
                v.x = acc.a[mi][nf][rr * 2 + 0] + bias[cg];
                v.y = acc.a[mi][nf][rr * 2 + 1] + bias[cg + 1];
                *reinterpret_cast<float2*>(Cf + (long)m * E_ + cg) = v;
            }
        }
    }
}

// ==================== fused flash attention (log2-domain running-max softmax) ====================
// Q pre-scaled by log2(e): energies are in log2 units, so max-subtraction,
// exp, and O-rescale all use exp2f (native MUFU EX2, no scale FMA).
// P = exp2(s - m) in (0,1] -> fits fp16 (the R15 NaN lesson).
// 2 CTAs/SM, 128 threads, Q-tile 64 rows. energy 3-term; AV 1-term.
#define STRK 144
#define STRV 272
#define F_KLO  (128 * STRK)            // 18432
#define F_V    (2 * 128 * STRK)        // 36864
#define FSTAGE (F_V + 64 * STRV)       // 54272
#define SMEM_FLASH (2 * FSTAGE)        // 108544  (x2 CTAs = 217088 <= 227KB)

__device__ __forceinline__ void flash_issue(uint32_t sbase, int stg, int tok0,
    const __half* Kh, const __half* Kl, const __half* Vt, int tid)
{
    const uint32_t s0 = sbase + stg * FSTAGE;
    #pragma unroll
    for (int i = 0; i < 8; i++) {
        int idx = tid + i * 128;
        int r = idx >> 3, c8 = idx & 7;
        uint32_t so = r * STRK + c8 * 16;
        CP_A16(s0 + so,          Kh + (long)(tok0 + r) * 1024 + c8 * 8);
        CP_A16(s0 + F_KLO + so,  Kl + (long)(tok0 + r) * 1024 + c8 * 8);
    }
    #pragma unroll
    for (int i = 0; i < 8; i++) {
        int idx = tid + i * 128;
        int r = idx >> 4, c = idx & 15;
        CP_A16(s0 + F_V + r * STRV + c * 16,  Vt + (long)r * N_ + tok0 + c * 8);
    }
}

__global__ void __launch_bounds__(128, 2)
flash_attn(const __half* __restrict__ qh_g, const __half* __restrict__ ql_g,
           const __half* __restrict__ kh_g, const __half* __restrict__ kl_g,
           const __half* __restrict__ vt_g, __half* __restrict__ c_g)
{
    extern __shared__ char smem[];
    const uint32_t sbase = smem_to_u32(smem);
    const int tid = threadIdx.x, warp = tid >> 5, lane = tid & 31;
    const int bh = blockIdx.y, b = bh >> 4, h = bh & 15;
    const int q0 = blockIdx.x * 64;

    const __half* Qh = qh_g + (long)(b * 1024 + q0) * 1024 + h * 64;
    const __half* Ql = ql_g + (long)(b * 1024 + q0) * 1024 + h * 64;
    const __half* Kh = kh_g + (long)(b * 1024) * 1024 + h * 64;
    const __half* Kl = kl_g + (long)(b * 1024) * 1024 + h * 64;
    const __half* Vt = vt_g + (long)bh * D_ * N_;

    const int lrow = (lane & 7) | (((lane >> 3) & 1) << 3);
    const int lk8b = (lane >> 4) * 16;

    // ---- stage Q tile (64 rows) through stage-0 K area, lift frags ----
    #pragma unroll
    for (int i = 0; i < 4; i++) {
        int idx = tid + i * 128;
        int r = idx >> 3, c8 = idx & 7;
        *reinterpret_cast<uint4*>(smem + r * STRK + c8 * 16) =
            *reinterpret_cast<const uint4*>(Qh + (long)r * 1024 + c8 * 8);
        *reinterpret_cast<uint4*>(smem + F_KLO + r * STRK + c8 * 16) =
            *reinterpret_cast<const uint4*>(Ql + (long)r * 1024 + c8 * 8);
    }
    __syncthreads();
    uint32_t qh[4][4], ql[4][4];
    #pragma unroll
    for (int ks = 0; ks < 4; ks++) {
        uint32_t ao = sbase + (uint32_t)(warp * 16 + lrow) * STRK + ks * 32 + lk8b;
        LDSM_X4(qh[ks], ao);
        LDSM_X4(ql[ks], ao + F_KLO);
    }
    __syncthreads();

    float m0 = -INFINITY, m1 = -INFINITY;
    float l0 = 0.f, l1 = 0.f;
    float o[8][4];
    #pragma unroll
    for (int nf = 0; nf < 8; nf++)
        #pragma unroll
        for (int r = 0; r < 4; r++) o[nf][r] = 0.f;

    flash_issue(sbase, 0, 0, Kh, Kl, Vt, tid);
    CP_COMMIT();
    CP_WAIT0();
    __syncthreads();

    for (int t = 0; t < 8; t++) {
        const uint32_t s0 = sbase + (t & 1) * FSTAGE;
        if (t + 1 < 8) {
            flash_issue(sbase, (t + 1) & 1, (t + 1) * 128, Kh, Kl, Vt, tid);
            CP_COMMIT();
        }

        // ---- energy (3-term), K-fragment double buffer; result in log2 units ----
        float s[16][4];
        #pragma unroll
        for (int nf = 0; nf < 16; nf++)
            #pragma unroll
            for (int r = 0; r < 4; r++) s[nf][r] = 0.f;

        {
            uint32_t ebH[2][4], ebL[2][4];
            {
                uint32_t bo = s0 + (uint32_t)lrow * STRK + lk8b;
                LDSM_X4(ebH[0], bo);
                LDSM_X4(ebL[0], bo + F_KLO);
            }
            #pragma unroll
            for (int it = 0; it < 32; it++) {
                const int ks = it >> 3, nf2 = it & 7;
                const int cur = it & 1, nxt = cur ^ 1;
                if (it < 31) {
                    const int it2 = it + 1, ks2 = it2 >> 3, nf22 = it2 & 7;
                    uint32_t bo = s0 + (uint32_t)(nf22 * 16 + lrow) * STRK + ks2 * 32 + lk8b;
                    LDSM_X4(ebH[nxt], bo);
                    LDSM_X4(ebL[nxt], bo + F_KLO);
                }
                MMA_F16(s[2 * nf2],     qh[ks], ebH[cur][0], ebH[cur][2]);
                MMA_F16(s[2 * nf2 + 1], qh[ks], ebH[cur][1], ebH[cur][3]);
                MMA_F16(s[2 * nf2],     qh[ks], ebL[cur][0], ebL[cur][2]);
                MMA_F16(s[2 * nf2 + 1], qh[ks], ebL[cur][1], ebL[cur][3]);
                MMA_F16(s[2 * nf2],     ql[ks], ebH[cur][0], ebH[cur][2]);
                MMA_F16(s[2 * nf2 + 1], ql[ks], ebH[cur][1], ebH[cur][3]);
            }
        }

        // ---- online softmax in log2 domain ----
        float mx0 = -INFINITY, mx1 = -INFINITY;
        #pragma unroll
        for (int nf = 0; nf < 16; nf++) {
            mx0 = fmaxf(mx0, fmaxf(s[nf][0], s[nf][1]));
            mx1 = fmaxf(mx1, fmaxf(s[nf][2], s[nf][3]));
        }
        mx0 = fmaxf(mx0, __shfl_xor_sync(0xffffffffu, mx0, 1));
        mx0 = fmaxf(mx0, __shfl_xor_sync(0xffffffffu, mx0, 2));
        mx1 = fmaxf(mx1, __shfl_xor_sync(0xffffffffu, mx1, 1));
        mx1 = fmaxf(mx1, __shfl_xor_sync(0xffffffffu, mx1, 2));
        const float mn0 = fmaxf(m0, mx0), mn1 = fmaxf(m1, mx1);
        const float sc0 = exp2f(m0 - mn0), sc1 = exp2f(m1 - mn1);
        m0 = mn0; m1 = mn1;

        float sum0 = 0.f, sum1 = 0.f;
        #pragma unroll
        for (int nf = 0; nf < 16; nf++) {
            s[nf][0] = exp2f(s[nf][0] - mn0);
            s[nf][1] = exp2f(s[nf][1] - mn0);
            s[nf][2] = exp2f(s[nf][2] - mn1);
            s[nf][3] = exp2f(s[nf][3] - mn1);
            sum0 += s[nf][0] + s[nf][1];
            sum1 += s[nf][2] + s[nf][3];
        }
        sum0 += __shfl_xor_sync(0xffffffffu, sum0, 1);
        sum0 += __shfl_xor_sync(0xffffffffu, sum0, 2);
        sum1 += __shfl_xor_sync(0xffffffffu, sum1, 1);
        sum1 += __shfl_xor_sync(0xffffffffu, sum1, 2);
        l0 = l0 * sc0 + sum0;
        l1 = l1 * sc1 + sum1;
        #pragma unroll
        for (int nf = 0; nf < 8; nf++) {
            o[nf][0] *= sc0; o[nf][1] *= sc0;
            o[nf][2] *= sc1; o[nf][3] *= sc1;
        }

        // ---- AV (1-term: P_hi x single V^T), V-fragment double buffer ----
        {
            uint32_t vb[2][4];
            {
                uint32_t vo = s0 + F_V + (uint32_t)lrow * STRV + lk8b;
                LDSM_X4(vb[0], vo);
            }
            #pragma unroll
            for (int kv = 0; kv < 8; kv++) {
                const float* f0 = s[2 * kv];
                const float* f1 = s[2 * kv + 1];
                uint32_t aH[4];
                aH[0] = packh(f0[0], f0[1]);
                aH[1] = packh(f0[2], f0[3]);
                aH[2] = packh(f1[0], f1[1]);
                aH[3] = packh(f1[2], f1[3]);
                #pragma unroll
                for (int nd2 = 0; nd2 < 4; nd2++) {
                    const int it = kv * 4 + nd2;
                    const int cur = it & 1, nxt = cur ^ 1;
                    if (it < 31) {
                        const int it2 = it + 1, kv2 = it2 >> 2, nd22 = it2 & 3;
                        uint32_t vo = s0 + F_V + (uint32_t)(nd22 * 16 + lrow) * STRV + kv2 * 32 + lk8b;
                        LDSM_X4(vb[nxt], vo);
                    }
                    MMA_F16(o[2 * nd2],     aH, vb[cur][0], vb[cur][2]);
                    MMA_F16(o[2 * nd2 + 1], aH, vb[cur][1], vb[cur][3]);
                }
            }
        }

        if (t + 1 < 8) { CP_WAIT0(); __syncthreads(); }
    }

    // ---- epilogue: normalize by 1/(l * sqrt(E)), store ctx single fp16 ----
    const float inv0 = 1.0f / (l0 * 32.0f);
    const float inv1 = 1.0f / (l1 * 32.0f);
    const int gr = b * 1024 + q0 + warp * 16 + (lane >> 2);
    const int colb = h * 64 + (lane & 3) * 2;
    #pragma unroll
    for (int nf = 0; nf < 8; nf++) {
        int col = colb + nf * 8;
        float v0 = o[nf][0] * inv0, v1 = o[nf][1] * inv0;
        float v2 = o[nf][2] * inv1, v3 = o[nf][3] * inv1;
        *reinterpret_cast<uint32_t*>(c_g + (long)gr * 1024 + col) = packh(v0, v1);
        *reinterpret_cast<uint32_t*>(c_g + (long)(gr + 8) * 1024 + col) = packh(v2, v3);
    }
}

// ==================== launch ====================
extern "C" void kernel_launch(void* const* d_in, const int* in_sizes, int n_in,
                              void* d_out, int out_size)
{
    const float* x  = (const float*)d_in[0];
    const float* Wq = (const float*)d_in[1];
    const float* bq = (const float*)d_in[2];
    const float* Wk = (const float*)d_in[3];
    const float* bk = (const float*)d_in[4];
    const float* Wv = (const float*)d_in[5];
    const float* bv = (const float*)d_in[6];
    const float* Wo = (const float*)d_in[7];
    const float* bo = (const float*)d_in[8];
    float* out = (float*)d_out;

    __half *xh, *xl, *wqh, *wql, *wkh, *wkl, *wvh, *woh;
    __half *qh, *ql, *kh, *kl, *vt, *c;
    cudaGetSymbolAddress((void**)&xh, g_xh);   cudaGetSymbolAddress((void**)&xl, g_xl);
    cudaGetSymbolAddress((void**)&wqh, g_wqh); cudaGetSymbolAddress((void**)&wql, g_wql);
    cudaGetSymbolAddress((void**)&wkh, g_wkh); cudaGetSymbolAddress((void**)&wkl, g_wkl);
    cudaGetSymbolAddress((void**)&wvh, g_wvh); cudaGetSymbolAddress((void**)&woh, g_woh);
    cudaGetSymbolAddress((void**)&qh, g_qh);   cudaGetSymbolAddress((void**)&ql, g_ql);
    cudaGetSymbolAddress((void**)&kh, g_kh);   cudaGetSymbolAddress((void**)&kl, g_kl);
    cudaGetSymbolAddress((void**)&vt, g_vt);   cudaGetSymbolAddress((void**)&c, g_c);

    cudaFuncSetAttribute(gemm_qkv,  cudaFuncAttributeMaxDynamicSharedMemorySize, GSMEM);
    cudaFuncSetAttribute(gemm_out,  cudaFuncAttributeMaxDynamicSharedMemorySize, OSMEM);
    cudaFuncSetAttribute(flash_attn, cudaFuncAttributeMaxDynamicSharedMemorySize, SMEM_FLASH);

    // ---- one merged split launch (x + 4 weights); lo only for x/Wq/Wk ----
    split_all<<<2048, 256>>>(x, Wq, Wk, Wv, Wo,
                             xh, xl, wqh, wql, wkh, wkl, wvh, woh);

    // ---- merged QKV projections (Q/K 3-term, V 1-term; Q scaled by log2e) ----
    {
        dim3 g(24, MTOT / 128);
        gemm_qkv<<<g, 256, GSMEM>>>(xh, xl, wqh, wql, wkh, wkl, wvh,
                                    bq, bk, bv, qh, ql, kh, kl, vt);
    }

    // ---- fused attention (log2-domain softmax with running max) ----
    {
        dim3 g(N_ / 64, BHN);
        flash_attn<<<g, 128, SMEM_FLASH>>>(qh, ql, kh, kl, vt, c);
    }

    // ---- output projection (1-term) ----
    {
        dim3 g(E_ / 128, MTOT / 128);
        gemm_out<<<g, 256, OSMEM>>>(c, woh, bo, out);
    }
}

// round 17
// speedup vs baseline: 1.0751x; 1.0751x over previous
#include <cuda_runtime.h>
#include <cuda_fp16.h>
#include <cstdint>
#include <math.h>

// Problem constants
#define B_  4
#define N_  1024
#define E_  1024
#define H_  16
#define D_  64
#define MTOT (B_ * N_)   // 4096
#define BHN  (B_ * H_)   // 64

// ==================== mma.sync / ldmatrix / cp.async helpers (fp16) ====================
__device__ __forceinline__ uint32_t smem_to_u32(const void* p) {
    uint32_t a;
    asm("{ .reg .u64 t; cvta.to.shared.u64 t, %1; cvt.u32.u64 %0, t; }" : "=r"(a) : "l"(p));
    return a;
}
#define LDSM_X4(R, ADDR) \
    asm volatile("ldmatrix.sync.aligned.m8n8.x4.shared.b16 {%0,%1,%2,%3}, [%4];" \
        : "=r"((R)[0]), "=r"((R)[1]), "=r"((R)[2]), "=r"((R)[3]) : "r"(ADDR))
#define MMA_F16(D, A, B0, B1) \
    asm("mma.sync.aligned.m16n8k16.row.col.f32.f16.f16.f32 " \
        "{%0,%1,%2,%3}, {%4,%5,%6,%7}, {%8,%9}, {%0,%1,%2,%3};" \
        : "+f"((D)[0]), "+f"((D)[1]), "+f"((D)[2]), "+f"((D)[3]) \
        : "r"((A)[0]), "r"((A)[1]), "r"((A)[2]), "r"((A)[3]), "r"(B0), "r"(B1))
#define CP_A16(DST, SRC) \
    asm volatile("cp.async.ca.shared.global [%0], [%1], 16;" :: "r"(DST), "l"(SRC))
#define CP_COMMIT() asm volatile("cp.async.commit_group;" ::: "memory")
#define CP_WAIT0()  asm volatile("cp.async.wait_group 0;" ::: "memory")

// pack two fp32 -> fp16x2 (lo element in low 16 bits)
__device__ __forceinline__ uint32_t packh(float lo, float hi) {
    uint32_t d;
    asm("cvt.rn.f16x2.f32 %0, %1, %2;" : "=r"(d) : "f"(hi), "f"(lo));
    return d;
}
__device__ __forceinline__ float toh(float v) {
    return __half2float(__float2half(v));
}

// ==================== scratch (device globals) ====================
__device__ __half g_xh[MTOT * E_], g_xl[MTOT * E_];
__device__ __half g_wqh[E_ * E_], g_wql[E_ * E_];
__device__ __half g_wkh[E_ * E_], g_wkl[E_ * E_];
__device__ __half g_wvh[E_ * E_];
__device__ __half g_woh[E_ * E_];
__device__ __half g_qh[MTOT * E_], g_ql[MTOT * E_];
__device__ __half g_kh[MTOT * E_], g_kl[MTOT * E_];
__device__ __half g_vt[BHN * D_ * N_];        // V^T single fp16: [bh][d][tok]
__device__ __half g_c[MTOT * E_];             // ctx single fp16

// ==================== merged fp32 -> fp16 hi/lo split (4 float4 / thread) ====================
// lo residual stored only for x, Wq, Wk (V/out projections are 1-term)
__global__ __launch_bounds__(256)
void split_all(const float* __restrict__ x,
               const float* __restrict__ wq, const float* __restrict__ wk,
               const float* __restrict__ wv, const float* __restrict__ wo,
               __half* __restrict__ xh, __half* __restrict__ xl,
               __half* __restrict__ wqh, __half* __restrict__ wql,
               __half* __restrict__ wkh, __half* __restrict__ wkl,
               __half* __restrict__ wvh, __half* __restrict__ woh)
{
    int blk = blockIdx.x;
    const float* in;
    __half *hi, *lo;
    int base;
    if (blk < 1024)      { in = x;  hi = xh;  lo = xl;  base = blk; }
    else if (blk < 1280) { in = wq; hi = wqh; lo = wql; base = blk - 1024; }
    else if (blk < 1536) { in = wk; hi = wkh; lo = wkl; base = blk - 1280; }
    else if (blk < 1792) { in = wv; hi = wvh; lo = nullptr; base = blk - 1536; }
    else                 { in = wo; hi = woh; lo = nullptr; base = blk - 1792; }

    const long off = (long)base * 4096 + threadIdx.x * 4;
    float4 v[4];
    #pragma unroll
    for (int j = 0; j < 4; j++)
        v[j] = *reinterpret_cast<const float4*>(in + off + j * 1024);
    #pragma unroll
    for (int j = 0; j < 4; j++) {
        long i = off + j * 1024;
        float vv[4] = {v[j].x, v[j].y, v[j].z, v[j].w};
        uint2 hw;
        hw.x = packh(vv[0], vv[1]);
        hw.y = packh(vv[2], vv[3]);
        *reinterpret_cast<uint2*>(hi + i) = hw;
        if (lo) {
            uint2 lw;
            lw.x = packh(vv[0] - toh(vv[0]), vv[1] - toh(vv[1]));
            lw.y = packh(vv[2] - toh(vv[2]), vv[3] - toh(vv[3]));
            *reinterpret_cast<uint2*>(lo + i) = lw;
        }
    }
}

// ==================== pipelined split-fp16 GEMM core (QKV) ====================
#define GSTR   80
#define G_ALO  10240
#define G_BHI  20480
#define G_BLO  30720
#define GSTAGE 40960
#define GSMEM  (2 * GSTAGE)   // 81920

struct GemmAcc { float a[2][8][4]; };

__device__ __forceinline__ void gemm_issue(uint32_t sbase, int stg,
    const __half* pAh, const __half* pAl,
    const __half* pBh, const __half* pBl, int tid, int nterms)
{
    const uint32_t s0 = sbase + stg * GSTAGE;
    #pragma unroll
    for (int i = 0; i < 2; i++) {
        int c = tid + i * 256;
        int r = c >> 2, k8 = c & 3;
        uint32_t so = r * GSTR + k8 * 16;
        CP_A16(s0 + so,          pAh + (long)r * E_ + k8 * 8);
        CP_A16(s0 + G_BHI + so,  pBh + (long)r * E_ + k8 * 8);
        if (nterms >= 3) CP_A16(s0 + G_ALO + so, pAl + (long)r * E_ + k8 * 8);
        if (nterms >= 2) CP_A16(s0 + G_BLO + so, pBl + (long)r * E_ + k8 * 8);
    }
}

// nterms: 3 = HH+HL+LH (Q/K), 1 = HH only (V)
__device__ __forceinline__ void gemm_compute(uint32_t sbase, int stg, GemmAcc& acc,
                                             int wm, int wn, int lrow, int lk8b, int nterms)
{
    const uint32_t s0 = sbase + stg * GSTAGE;

    uint32_t aH[2][2][4], aL[2][2][4];   // [ks][mi]
    #pragma unroll
    for (int ks = 0; ks < 2; ks++)
        #pragma unroll
        for (int mi = 0; mi < 2; mi++) {
            uint32_t ao = s0 + (uint32_t)(wm * 32 + mi * 16 + lrow) * GSTR + ks * 32 + lk8b;
            LDSM_X4(aH[ks][mi], ao);
            if (nterms >= 3) LDSM_X4(aL[ks][mi], ao + G_ALO);
        }

    uint32_t bH[2][4], bL[2][4];
    {
        uint32_t bo = s0 + G_BHI + (uint32_t)(wn * 64 + lrow) * GSTR + lk8b;
        LDSM_X4(bH[0], bo);
        if (nterms >= 2) LDSM_X4(bL[0], bo + (G_BLO - G_BHI));
    }

    #pragma unroll
    for (int it = 0; it < 8; it++) {
        const int ks = it >> 2, nj = it & 3;
        const int cur = it & 1, nxt = cur ^ 1;
        if (it < 7) {
            const int it2 = it + 1, ks2 = it2 >> 2, nj2 = it2 & 3;
            uint32_t bo = s0 + G_BHI + (uint32_t)(wn * 64 + nj2 * 16 + lrow) * GSTR + ks2 * 32 + lk8b;
            LDSM_X4(bH[nxt], bo);
            if (nterms >= 2) LDSM_X4(bL[nxt], bo + (G_BLO - G_BHI));
        }
        MMA_F16(acc.a[0][2 * nj],     aH[ks][0], bH[cur][0], bH[cur][2]);
        MMA_F16(acc.a[0][2 * nj + 1], aH[ks][0], bH[cur][1], bH[cur][3]);
        MMA_F16(acc.a[1][2 * nj],     aH[ks][1], bH[cur][0], bH[cur][2]);
        MMA_F16(acc.a[1][2 * nj + 1], aH[ks][1], bH[cur][1], bH[cur][3]);
        if (nterms >= 2) {
            MMA_F16(acc.a[0][2 * nj],     aH[ks][0], bL[cur][0], bL[cur][2]);
            MMA_F16(acc.a[0][2 * nj + 1], aH[ks][0], bL[cur][1], bL[cur][3]);
            MMA_F16(acc.a[1][2 * nj],     aH[ks][1], bL[cur][0], bL[cur][2]);
            MMA_F16(acc.a[1][2 * nj + 1], aH[ks][1], bL[cur][1], bL[cur][3]);
        }
        if (nterms >= 3) {
            MMA_F16(acc.a[0][2 * nj],     aL[ks][0], bH[cur][0], bH[cur][2]);
            MMA_F16(acc.a[0][2 * nj + 1], aL[ks][0], bH[cur][1], bH[cur][3]);
            MMA_F16(acc.a[1][2 * nj],     aL[ks][1], bH[cur][0], bH[cur][2]);
            MMA_F16(acc.a[1][2 * nj + 1], aL[ks][1], bH[cur][1], bH[cur][3]);
        }
    }
}

// ---- merged QKV projection: Q/K 3-term, V 1-term ----
// Grid: x = M tile (32), y = weight-col tile (24, ordered Q,K,V) so the
// cheap 1-term V CTAs launch LAST -> backfill scheduler pads the tail
// waves with short jobs (LPT ordering).
__global__ void __launch_bounds__(256, 2)
gemm_qkv(const __half* __restrict__ Ah, const __half* __restrict__ Al,
         const __half* __restrict__ wqh, const __half* __restrict__ wql,
         const __half* __restrict__ wkh, const __half* __restrict__ wkl,
         const __half* __restrict__ wvh,
         const float* __restrict__ bq, const float* __restrict__ bk, const float* __restrict__ bv,
         __half* __restrict__ qh, __half* __restrict__ ql,
         __half* __restrict__ kh, __half* __restrict__ kl,
         __half* __restrict__ vt)
{
    extern __shared__ char smem[];
    const uint32_t sbase = smem_to_u32(smem);
    const int tid = threadIdx.x, warp = tid >> 5, lane = tid & 31;
    const int wm = warp & 3, wn = warp >> 2;
    const int lrow = (lane & 7) | (((lane >> 3) & 1) << 3);
    const int lk8b = (lane >> 4) * 16;

    const int widx = blockIdx.y >> 3;          // 0=Q, 1=K, 2=V (V last)
    const int col0 = (blockIdx.y & 7) * 128;
    const int row0 = blockIdx.x * 128;
    const int nterms = (widx == 2) ? 1 : 3;

    const __half* Bh = (widx == 0) ? wqh : (widx == 1) ? wkh : wvh;
    const __half* Bl = (widx == 0) ? wql : wkl;   // unused when nterms==1
    const float* bias = (widx == 0) ? bq : (widx == 1) ? bk : bv;

    GemmAcc acc;
    #pragma unroll
    for (int mi = 0; mi < 2; mi++)
        #pragma unroll
        for (int nj = 0; nj < 8; nj++)
            #pragma unroll
            for (int r = 0; r < 4; r++) acc.a[mi][nj][r] = 0.f;

    const __half* pAh = Ah + (long)row0 * E_;
    const __half* pAl = Al + (long)row0 * E_;
    const __half* pBh = Bh + (long)col0 * E_;
    const __half* pBl = Bl + (long)col0 * E_;

    const int nch = E_ >> 5;
    gemm_issue(sbase, 0, pAh, pAl, pBh, pBl, tid, nterms);
    CP_COMMIT();
    CP_WAIT0();
    __syncthreads();
    for (int kc = 0; kc < nch; kc++) {
        if (kc + 1 < nch) {
            gemm_issue(sbase, (kc + 1) & 1, pAh + (kc + 1) * 32, pAl + (kc + 1) * 32,
                       pBh + (kc + 1) * 32, pBl + (kc + 1) * 32, tid, nterms);
            CP_COMMIT();
        }
        gemm_compute(sbase, kc & 1, acc, wm, wn, lrow, lk8b, nterms);
        if (kc + 1 < nch) { CP_WAIT0(); __syncthreads(); }
    }

    #pragma unroll
    for (int mi = 0; mi < 2; mi++) {
        int rg = row0 + wm * 32 + mi * 16 + (lane >> 2);
        #pragma unroll
        for (int nf = 0; nf < 8; nf++) {
            int cg = col0 + wn * 64 + nf * 8 + (lane & 3) * 2;
            #pragma unroll
            for (int rr = 0; rr < 2; rr++) {
                int m = rg + rr * 8;
                float v0 = acc.a[mi][nf][rr * 2 + 0] + bias[cg];
                float v1 = acc.a[mi][nf][rr * 2 + 1] + bias[cg + 1];
                if (widx != 2) {
                    __half* dh = (widx == 0) ? qh : kh;
                    __half* dl = (widx == 0) ? ql : kl;
                    long o = (long)m * E_ + cg;
                    *reinterpret_cast<uint32_t*>(dh + o) = packh(v0, v1);
                    *reinterpret_cast<uint32_t*>(dl + o) = packh(v0 - toh(v0), v1 - toh(v1));
                } else {
                    int b = m >> 10, tok = m & 1023;
                    int hh = cg >> 6, dc0 = cg & 63;
                    long o0 = ((long)(b * H_ + hh) * D_ + dc0) * N_ + tok;
                    vt[o0] = __float2half(v0);
                    vt[o0 + N_] = __float2half(v1);
                }
            }
        }
    }
}

// ---- output projection: 1-term ----
#define OSTR   80
#define O_B    10240
#define OSTAGE 20480
#define OSMEM  (2 * OSTAGE)   // 40960

__global__ void __launch_bounds__(256, 2)
gemm_out(const __half* __restrict__ A, const __half* __restrict__ Bh,
         const float* __restrict__ bias, float* __restrict__ Cf)
{
    extern __shared__ char smem[];
    const uint32_t sbase = smem_to_u32(smem);
    const int tid = threadIdx.x, warp = tid >> 5, lane = tid & 31;
    const int wm = warp & 3, wn = warp >> 2;
    const int lrow = (lane & 7) | (((lane >> 3) & 1) << 3);
    const int lk8b = (lane >> 4) * 16;

    const int col0 = blockIdx.x * 128;
    const int row0 = blockIdx.y * 128;

    GemmAcc acc;
    #pragma unroll
    for (int mi = 0; mi < 2; mi++)
        #pragma unroll
        for (int nj = 0; nj < 8; nj++)
            #pragma unroll
            for (int r = 0; r < 4; r++) acc.a[mi][nj][r] = 0.f;

    const __half* pA  = A  + (long)row0 * E_;
    const __half* pBh = Bh + (long)col0 * E_;

    auto issue = [&](int stg, int kc) {
        const uint32_t s0 = sbase + stg * OSTAGE;
        #pragma unroll
        for (int i = 0; i < 2; i++) {
            int c = tid + i * 256;
            int r = c >> 2, k8 = c & 3;
            uint32_t so = r * OSTR + k8 * 16;
            CP_A16(s0 + so,        pA  + (long)r * E_ + kc * 32 + k8 * 8);
            CP_A16(s0 + O_B + so,  pBh + (long)r * E_ + kc * 32 + k8 * 8);
        }
    };

    const int nch = E_ >> 5;
    issue(0, 0);
    CP_COMMIT();
    CP_WAIT0();
    __syncthreads();
    for (int kc = 0; kc < nch; kc++) {
        if (kc + 1 < nch) { issue((kc + 1) & 1, kc + 1); CP_COMMIT(); }
        {
            const uint32_t s0 = sbase + (kc & 1) * OSTAGE;
            uint32_t aF[2][2][4];
            #pragma unroll
            for (int ks = 0; ks < 2; ks++)
                #pragma unroll
                for (int mi = 0; mi < 2; mi++) {
                    uint32_t ao = s0 + (uint32_t)(wm * 32 + mi * 16 + lrow) * OSTR + ks * 32 + lk8b;
                    LDSM_X4(aF[ks][mi], ao);
                }
            uint32_t bB[2][4];
            {
                uint32_t bo = s0 + O_B + (uint32_t)(wn * 64 + lrow) * OSTR + lk8b;
                LDSM_X4(bB[0], bo);
            }
            #pragma unroll
            for (int it = 0; it < 8; it++) {
                const int ks = it >> 2, nj = it & 3;
                const int cur = it & 1, nxt = cur ^ 1;
                if (it < 7) {
                    const int it2 = it + 1, ks2 = it2 >> 2, nj2 = it2 & 3;
                    uint32_t bo = s0 + O_B + (uint32_t)(wn * 64 + nj2 * 16 + lrow) * OSTR + ks2 * 32 + lk8b;
                    LDSM_X4(bB[nxt], bo);
                }
                MMA_F16(acc.a[0][2 * nj],     aF[ks][0], bB[cur][0], bB[cur][2]);
                MMA_F16(acc.a[0][2 * nj + 1], aF[ks][0], bB[cur][1], bB[cur][3]);
                MMA_F16(acc.a[1][2 * nj],     aF[ks][1], bB[cur][0], bB[cur][2]);
                MMA_F16(acc.a[1][2 * nj + 1], aF[ks][1], bB[cur][1], bB[cur][3]);
            }
        }
        if (kc + 1 < nch) { CP_WAIT0(); __syncthreads(); }
    }

    #pragma unroll
    for (int mi = 0; mi < 2; mi++) {
        int rg = row0 + wm * 32 + mi * 16 + (lane >> 2);
        #pragma unroll
        for (int nf = 0; nf < 8; nf++) {
            int cg = col0 + wn * 64 + nf * 8 + (lane & 3) * 2;
            #pragma unroll
            for (int rr = 0; rr < 2; rr++) {
                int m = rg + rr * 8;
                float2 v;
                v.x = acc.a[mi][nf][rr * 2 + 0] + bias[cg];
                v.y = acc.a[mi][nf][rr * 2 + 1] + bias[cg + 1];
                *reinterpret_cast<float2*>(Cf + (long)m * E_ + cg) = v;
            }
        }
    }
}

// ==================== fused flash attention (R14 champion version) ====================
// 2 CTAs/SM, 128 threads (4 warps), Q-tile 64 rows.
// energy 3-term; AV 1-term (P_hi x single V^T); ctx single fp16.
#define STRK 144
#define STRV 272
#define F_KLO  (128 * STRK)            // 18432
#define F_V    (2 * 128 * STRK)        // 36864
#define FSTAGE (F_V + 64 * STRV)       // 54272
#define SMEM_FLASH (2 * FSTAGE)        // 108544  (x2 CTAs = 217088 <= 227KB)

__device__ __forceinline__ void flash_issue(uint32_t sbase, int stg, int tok0,
    const __half* Kh, const __half* Kl, const __half* Vt, int tid)
{
    const uint32_t s0 = sbase + stg * FSTAGE;
    #pragma unroll
    for (int i = 0; i < 8; i++) {
        int idx = tid + i * 128;
        int r = idx >> 3, c8 = idx & 7;
        uint32_t so = r * STRK + c8 * 16;
        CP_A16(s0 + so,          Kh + (long)(tok0 + r) * 1024 + c8 * 8);
        CP_A16(s0 + F_KLO + so,  Kl + (long)(tok0 + r) * 1024 + c8 * 8);
    }
    #pragma unroll
    for (int i = 0; i < 8; i++) {
        int idx = tid + i * 128;
        int r = idx >> 4, c = idx & 15;
        CP_A16(s0 + F_V + r * STRV + c * 16,  Vt + (long)r * N_ + tok0 + c * 8);
    }
}

__global__ void __launch_bounds__(128, 2)
flash_attn(const __half* __restrict__ qh_g, const __half* __restrict__ ql_g,
           const __half* __restrict__ kh_g, const __half* __restrict__ kl_g,
           const __half* __restrict__ vt_g, __half* __restrict__ c_g)
{
    extern __shared__ char smem[];
    const uint32_t sbase = smem_to_u32(smem);
    const int tid = threadIdx.x, warp = tid >> 5, lane = tid & 31;
    const int bh = blockIdx.y, b = bh >> 4, h = bh & 15;
    const int q0 = blockIdx.x * 64;

    const __half* Qh = qh_g + (long)(b * 1024 + q0) * 1024 + h * 64;
    const __half* Ql = ql_g + (long)(b * 1024 + q0) * 1024 + h * 64;
    const __half* Kh = kh_g + (long)(b * 1024) * 1024 + h * 64;
    const __half* Kl = kl_g + (long)(b * 1024) * 1024 + h * 64;
    const __half* Vt = vt_g + (long)bh * D_ * N_;

    const int lrow = (lane & 7) | (((lane >> 3) & 1) << 3);
    const int lk8b = (lane >> 4) * 16;

    // ---- stage Q tile (64 rows) through stage-0 K area, lift frags ----
    #pragma unroll
    for (int i = 0; i < 4; i++) {
        int idx = tid + i * 128;
        int r = idx >> 3, c8 = idx & 7;
        *reinterpret_cast<uint4*>(smem + r * STRK + c8 * 16) =
            *reinterpret_cast<const uint4*>(Qh + (long)r * 1024 + c8 * 8);
        *reinterpret_cast<uint4*>(smem + F_KLO + r * STRK + c8 * 16) =
            *reinterpret_cast<const uint4*>(Ql + (long)r * 1024 + c8 * 8);
    }
    __syncthreads();
    uint32_t qh[4][4], ql[4][4];
    #pragma unroll
    for (int ks = 0; ks < 4; ks++) {
        uint32_t ao = sbase + (uint32_t)(warp * 16 + lrow) * STRK + ks * 32 + lk8b;
        LDSM_X4(qh[ks], ao);
        LDSM_X4(ql[ks], ao + F_KLO);
    }
    __syncthreads();

    float m0 = -INFINITY, m1 = -INFINITY;
    float l0 = 0.f, l1 = 0.f;
    float o[8][4];
    #pragma unroll
    for (int nf = 0; nf < 8; nf++)
        #pragma unroll
        for (int r = 0; r < 4; r++) o[nf][r] = 0.f;

    flash_issue(sbase, 0, 0, Kh, Kl, Vt, tid);
    CP_COMMIT();
    CP_WAIT0();
    __syncthreads();

    for (int t = 0; t < 8; t++) {
        const uint32_t s0 = sbase + (t & 1) * FSTAGE;
        if (t + 1 < 8) {
            flash_issue(sbase, (t + 1) & 1, (t + 1) * 128, Kh, Kl, Vt, tid);
            CP_COMMIT();
        }

        // ---- energy (3-term), K-fragment double buffer ----
        float s[16][4];
        #pragma unroll
        for (int nf = 0; nf < 16; nf++)
            #pragma unroll
            for (int r = 0; r < 4; r++) s[nf][r] = 0.f;

        {
            uint32_t ebH[2][4], ebL[2][4];
            {
                uint32_t bo = s0 + (uint32_t)lrow * STRK + lk8b;
                LDSM_X4(ebH[0], bo);
                LDSM_X4(ebL[0], bo + F_KLO);
            }
            #pragma unroll
            for (int it = 0; it < 32; it++) {
                const int ks = it >> 3, nf2 = it & 7;
                const int cur = it & 1, nxt = cur ^ 1;
                if (it < 31) {
                    const int it2 = it + 1, ks2 = it2 >> 3, nf22 = it2 & 7;
                    uint32_t bo = s0 + (uint32_t)(nf22 * 16 + lrow) * STRK + ks2 * 32 + lk8b;
                    LDSM_X4(ebH[nxt], bo);
                    LDSM_X4(ebL[nxt], bo + F_KLO);
                }
                MMA_F16(s[2 * nf2],     qh[ks], ebH[cur][0], ebH[cur][2]);
                MMA_F16(s[2 * nf2 + 1], qh[ks], ebH[cur][1], ebH[cur][3]);
                MMA_F16(s[2 * nf2],     qh[ks], ebL[cur][0], ebL[cur][2]);
                MMA_F16(s[2 * nf2 + 1], qh[ks], ebL[cur][1], ebL[cur][3]);
                MMA_F16(s[2 * nf2],     ql[ks], ebH[cur][0], ebH[cur][2]);
                MMA_F16(s[2 * nf2 + 1], ql[ks], ebH[cur][1], ebH[cur][3]);
            }
        }

        // ---- online softmax ----
        float mx0 = -INFINITY, mx1 = -INFINITY;
        #pragma unroll
        for (int nf = 0; nf < 16; nf++) {
            mx0 = fmaxf(mx0, fmaxf(s[nf][0], s[nf][1]));
            mx1 = fmaxf(mx1, fmaxf(s[nf][2], s[nf][3]));
        }
        mx0 = fmaxf(mx0, __shfl_xor_sync(0xffffffffu, mx0, 1));
        mx0 = fmaxf(mx0, __shfl_xor_sync(0xffffffffu, mx0, 2));
        mx1 = fmaxf(mx1, __shfl_xor_sync(0xffffffffu, mx1, 1));
        mx1 = fmaxf(mx1, __shfl_xor_sync(0xffffffffu, mx1, 2));
        const float mn0 = fmaxf(m0, mx0), mn1 = fmaxf(m1, mx1);
        const float sc0 = __expf(m0 - mn0), sc1 = __expf(m1 - mn1);
        m0 = mn0; m1 = mn1;

        float sum0 = 0.f, sum1 = 0.f;
        #pragma unroll
        for (int nf = 0; nf < 16; nf++) {
            s[nf][0] = __expf(s[nf][0] - mn0);
            s[nf][1] = __expf(s[nf][1] - mn0);
            s[nf][2] = __expf(s[nf][2] - mn1);
            s[nf][3] = __expf(s[nf][3] - mn1);
            sum0 += s[nf][0] + s[nf][1];
            sum1 += s[nf][2] + s[nf][3];
        }
        sum0 += __shfl_xor_sync(0xffffffffu, sum0, 1);
        sum0 += __shfl_xor_sync(0xffffffffu, sum0, 2);
        sum1 += __shfl_xor_sync(0xffffffffu, sum1, 1);
        sum1 += __shfl_xor_sync(0xffffffffu, sum1, 2);
        l0 = l0 * sc0 + sum0;
        l1 = l1 * sc1 + sum1;
        #pragma unroll
        for (int nf = 0; nf < 8; nf++) {
            o[nf][0] *= sc0; o[nf][1] *= sc0;
            o[nf][2] *= sc1; o[nf][3] *= sc1;
        }

        // ---- AV (1-term: P_hi x single V^T), V-fragment double buffer ----
        {
            uint32_t vb[2][4];
            {
                uint32_t vo = s0 + F_V + (uint32_t)lrow * STRV + lk8b;
                LDSM_X4(vb[0], vo);
            }
            #pragma unroll
            for (int kv = 0; kv < 8; kv++) {
                const float* f0 = s[2 * kv];
                const float* f1 = s[2 * kv + 1];
                uint32_t aH[4];
                aH[0] = packh(f0[0], f0[1]);
                aH[1] = packh(f0[2], f0[3]);
                aH[2] = packh(f1[0], f1[1]);
                aH[3] = packh(f1[2], f1[3]);
                #pragma unroll
                for (int nd2 = 0; nd2 < 4; nd2++) {
                    const int it = kv * 4 + nd2;
                    const int cur = it & 1, nxt = cur ^ 1;
                    if (it < 31) {
                        const int it2 = it + 1, kv2 = it2 >> 2, nd22 = it2 & 3;
                        uint32_t vo = s0 + F_V + (uint32_t)(nd22 * 16 + lrow) * STRV + kv2 * 32 + lk8b;
                        LDSM_X4(vb[nxt], vo);
                    }
                    MMA_F16(o[2 * nd2],     aH, vb[cur][0], vb[cur][2]);
                    MMA_F16(o[2 * nd2 + 1], aH, vb[cur][1], vb[cur][3]);
                }
            }
        }

        if (t + 1 < 8) { CP_WAIT0(); __syncthreads(); }
    }

    // ---- epilogue: normalize by 1/(l * sqrt(E)), store ctx single fp16 ----
    const float inv0 = 1.0f / (l0 * 32.0f);
    const float inv1 = 1.0f / (l1 * 32.0f);
    const int gr = b * 1024 + q0 + warp * 16 + (lane >> 2);
    const int colb = h * 64 + (lane & 3) * 2;
    #pragma unroll
    for (int nf = 0; nf < 8; nf++) {
        int col = colb + nf * 8;
        float v0 = o[nf][0] * inv0, v1 = o[nf][1] * inv0;
        float v2 = o[nf][2] * inv1, v3 = o[nf][3] * inv1;
        *reinterpret_cast<uint32_t*>(c_g + (long)gr * 1024 + col) = packh(v0, v1);
        *reinterpret_cast<uint32_t*>(c_g + (long)(gr + 8) * 1024 + col) = packh(v2, v3);
    }
}

// ==================== launch ====================
extern "C" void kernel_launch(void* const* d_in, const int* in_sizes, int n_in,
                              void* d_out, int out_size)
{
    const float* x  = (const float*)d_in[0];
    const float* Wq = (const float*)d_in[1];
    const float* bq = (const float*)d_in[2];
    const float* Wk = (const float*)d_in[3];
    const float* bk = (const float*)d_in[4];
    const float* Wv = (const float*)d_in[5];
    const float* bv = (const float*)d_in[6];
    const float* Wo = (const float*)d_in[7];
    const float* bo = (const float*)d_in[8];
    float* out = (float*)d_out;

    __half *xh, *xl, *wqh, *wql, *wkh, *wkl, *wvh, *woh;
    __half *qh, *ql, *kh, *kl, *vt, *c;
    cudaGetSymbolAddress((void**)&xh, g_xh);   cudaGetSymbolAddress((void**)&xl, g_xl);
    cudaGetSymbolAddress((void**)&wqh, g_wqh); cudaGetSymbolAddress((void**)&wql, g_wql);
    cudaGetSymbolAddress((void**)&wkh, g_wkh); cudaGetSymbolAddress((void**)&wkl, g_wkl);
    cudaGetSymbolAddress((void**)&wvh, g_wvh); cudaGetSymbolAddress((void**)&woh, g_woh);
    cudaGetSymbolAddress((void**)&qh, g_qh);   cudaGetSymbolAddress((void**)&ql, g_ql);
    cudaGetSymbolAddress((void**)&kh, g_kh);   cudaGetSymbolAddress((void**)&kl, g_kl);
    cudaGetSymbolAddress((void**)&vt, g_vt);   cudaGetSymbolAddress((void**)&c, g_c);

    cudaFuncSetAttribute(gemm_qkv,  cudaFuncAttributeMaxDynamicSharedMemorySize, GSMEM);
    cudaFuncSetAttribute(gemm_out,  cudaFuncAttributeMaxDynamicSharedMemorySize, OSMEM);
    cudaFuncSetAttribute(flash_attn, cudaFuncAttributeMaxDynamicSharedMemorySize, SMEM_FLASH);

    // ---- one merged split launch (x + 4 weights); lo only for x/Wq/Wk ----
    split_all<<<2048, 256>>>(x, Wq, Wk, Wv, Wo,
                             xh, xl, wqh, wql, wkh, wkl, wvh, woh);

    // ---- merged QKV projections (Q/K 3-term, V 1-term; V tiles launch last) ----
    {
        dim3 g(MTOT / 128, 24);
        gemm_qkv<<<g, 256, GSMEM>>>(xh, xl, wqh, wql, wkh, wkl, wvh,
                                    bq, bk, bv, qh, ql, kh, kl, vt);
    }

    // ---- fused attention (R14 champion: 2 CTAs/SM, 64-row Q tiles) ----
    {
        dim3 g(N_ / 64, BHN);
        flash_attn<<<g, 128, SMEM_FLASH>>>(qh, ql, kh, kl, vt, c);
    }

    // ---- output projection (1-term) ----
    {
        dim3 g(E_ / 128, MTOT / 128);
        gemm_out<<<g, 256, OSMEM>>>(c, woh, bo, out);
    }
}